// round 6
// baseline (speedup 1.0000x reference)
#include <cuda_runtime.h>
#include <math.h>

#define B_ROWS 65536
#define C_CLS  1000
#define C4     250        // 1000 floats = 250 float4 per row
#define BETA_F 3.0f
#define DOT_BLOCKS 256

// ---- scratch (no allocations allowed) ----
__device__ int   g_counts[C_CLS * C_CLS];
__device__ float g_glp[B_ROWS];
__device__ int   g_pred[B_ROWS];
__device__ float g_scale[C_CLS];
__device__ float g_partial[DOT_BLOCKS];
__device__ int   g_is64;

// ---------------------------------------------------------------------------
// k0: zero the counts matrix and detect targets dtype (int32 vs int64).
// For int64 little-endian values in [0,1000), every odd 32-bit word is 0.
// ---------------------------------------------------------------------------
__global__ void k_zero(const int* __restrict__ tgt_words) {
    int i = blockIdx.x * blockDim.x + threadIdx.x;
    int stride = gridDim.x * blockDim.x;
    for (int j = i; j < C_CLS * C_CLS; j += stride) g_counts[j] = 0;
    if (i == 0) {
        int nz = 0;
        #pragma unroll 1
        for (int k = 1; k < 256; k += 2) nz |= tgt_words[k];
        g_is64 = (nz == 0) ? 1 : 0;
    }
}

// ---------------------------------------------------------------------------
// k1: one warp per row. Fused rowmax + argmax + sumexp + target-logit gather
// + scatter-count. 262 MB streamed once -> HBM-bound.
// ---------------------------------------------------------------------------
__global__ __launch_bounds__(256) void k_rows(
    const float* __restrict__ outp, const void* __restrict__ tgt)
{
    int warp = (blockIdx.x * 256 + threadIdx.x) >> 5;
    int lane = threadIdx.x & 31;
    if (warp >= B_ROWS) return;

    const float4* rp = (const float4*)(outp + (size_t)warp * C_CLS);

    float vals[32];
    float m  = -INFINITY;
    int   am = 0x7fffffff;

    // Batch 8 independent LDG.128 per lane (MLP), track lane-local max/argmax.
    #pragma unroll
    for (int i = 0; i < 8; i++) {
        int idx4 = lane + i * 32;
        float4 v;
        if (idx4 < C4) v = rp[idx4];
        else           v = make_float4(-INFINITY, -INFINITY, -INFINITY, -INFINITY);
        int base = idx4 * 4;
        vals[4*i+0] = v.x; vals[4*i+1] = v.y; vals[4*i+2] = v.z; vals[4*i+3] = v.w;
        if (v.x > m || (v.x == m && base + 0 < am)) { m = v.x; am = base + 0; }
        if (v.y > m || (v.y == m && base + 1 < am)) { m = v.y; am = base + 1; }
        if (v.z > m || (v.z == m && base + 2 < am)) { m = v.z; am = base + 2; }
        if (v.w > m || (v.w == m && base + 3 < am)) { m = v.w; am = base + 3; }
    }

    // Warp argmax-reduce (first-index tiebreak, matches jnp.argmax).
    #pragma unroll
    for (int off = 16; off; off >>= 1) {
        float om = __shfl_down_sync(0xffffffffu, m,  off);
        int   oa = __shfl_down_sync(0xffffffffu, am, off);
        if (om > m || (om == m && oa < am)) { m = om; am = oa; }
    }
    m  = __shfl_sync(0xffffffffu, m,  0);
    am = __shfl_sync(0xffffffffu, am, 0);

    // Sumexp over register-resident values (padding -INF -> exp = 0).
    float s = 0.0f;
    #pragma unroll
    for (int k = 0; k < 32; k++) s += __expf(vals[k] - m);
    #pragma unroll
    for (int off = 16; off; off >>= 1)
        s += __shfl_down_sync(0xffffffffu, s, off);

    if (lane == 0) {
        long long t = g_is64 ? ((const long long*)tgt)[warp]
                             : (long long)((const int*)tgt)[warp];
        float xt  = outp[(size_t)warp * C_CLS + (int)t];
        float glp = xt - m - __logf(s);
        g_glp[warp]  = glp;
        g_pred[warp] = am;
        atomicAdd(&g_counts[(int)t * C_CLS + am], 1);
    }
}

// ---------------------------------------------------------------------------
// k2: per-class row-sum of (cost_matrix + counts) -> scale[t] = beta/max(1,sum)
// One block per class row.
// ---------------------------------------------------------------------------
__global__ __launch_bounds__(256) void k_scale(const float* __restrict__ cost) {
    int r = blockIdx.x;
    float s = 0.0f;
    for (int c = threadIdx.x; c < C_CLS; c += 256) {
        int idx = r * C_CLS + c;
        s += cost[idx] + (float)g_counts[idx];
    }
    __shared__ float sh[256];
    sh[threadIdx.x] = s;
    __syncthreads();
    #pragma unroll
    for (int off = 128; off; off >>= 1) {
        if (threadIdx.x < off) sh[threadIdx.x] += sh[threadIdx.x + off];
        __syncthreads();
    }
    if (threadIdx.x == 0) g_scale[r] = BETA_F / fmaxf(1.0f, sh[0]);
}

// ---------------------------------------------------------------------------
// k3: per-sample gather + product, block tree-reduce to partials.
// Grid of 256x256 = exactly one thread per sample -> deterministic.
// ---------------------------------------------------------------------------
__global__ __launch_bounds__(256) void k_dot(
    const float* __restrict__ cost, const void* __restrict__ tgt)
{
    int b = blockIdx.x * 256 + threadIdx.x;
    float acc = 0.0f;
    if (b < B_ROWS) {
        long long t = g_is64 ? ((const long long*)tgt)[b]
                             : (long long)((const int*)tgt)[b];
        int p   = g_pred[b];
        int idx = (int)t * C_CLS + p;
        float cm = cost[idx] + (float)g_counts[idx];
        acc = g_glp[b] * cm * g_scale[(int)t];
    }
    __shared__ float sh[256];
    sh[threadIdx.x] = acc;
    __syncthreads();
    #pragma unroll
    for (int off = 128; off; off >>= 1) {
        if (threadIdx.x < off) sh[threadIdx.x] += sh[threadIdx.x + off];
        __syncthreads();
    }
    if (threadIdx.x == 0) g_partial[blockIdx.x] = sh[0];
}

// ---------------------------------------------------------------------------
// k4: final deterministic reduce of 256 partials -> -mean
// ---------------------------------------------------------------------------
__global__ __launch_bounds__(DOT_BLOCKS) void k_final(float* __restrict__ out) {
    __shared__ float sh[DOT_BLOCKS];
    sh[threadIdx.x] = g_partial[threadIdx.x];
    __syncthreads();
    #pragma unroll
    for (int off = DOT_BLOCKS / 2; off; off >>= 1) {
        if (threadIdx.x < off) sh[threadIdx.x] += sh[threadIdx.x + off];
        __syncthreads();
    }
    if (threadIdx.x == 0) out[0] = -sh[0] / (float)B_ROWS;
}

extern "C" void kernel_launch(void* const* d_in, const int* in_sizes, int n_in,
                              void* d_out, int out_size) {
    const float* outputs = (const float*)d_in[0];
    const void*  targets = d_in[1];
    const float* cost    = (const float*)d_in[2];
    float* out = (float*)d_out;

    k_zero <<<1024, 256>>>((const int*)targets);
    k_rows <<<B_ROWS / 8, 256>>>(outputs, targets);      // 8 warps/block
    k_scale<<<C_CLS, 256>>>(cost);
    k_dot  <<<DOT_BLOCKS, 256>>>(cost, targets);
    k_final<<<1, DOT_BLOCKS>>>(out);
}

// round 7
// speedup vs baseline: 1.2059x; 1.2059x over previous
#include <cuda_runtime.h>
#include <math.h>

#define B_ROWS 65536
#define C_CLS  1000
#define C4     250        // 1000 floats = 250 float4 per row
#define BETA_F 3.0f
#define DOT_BLOCKS 256

// ---- scratch (no allocations allowed) ----
__device__ int    g_counts[C_CLS * C_CLS];
__device__ float  g_cmn[C_CLS * C_CLS];     // (cost+counts)*scale, precomputed
__device__ float2 g_pair[B_ROWS];           // {glp, as_float(t*1000+p)}
__device__ float  g_partial[DOT_BLOCKS];
__device__ int    g_is64;
__device__ unsigned int g_done;

// ---------------------------------------------------------------------------
// k0: zero counts, reset last-block counter, parallel dtype detect.
// int64 targets in [0,1000): every odd 32-bit word is 0. Warp-ballot over the
// first 64 odd words (false-positive prob ~1e-192 for int32).
// ---------------------------------------------------------------------------
__global__ void k_zero(const int* __restrict__ tgt_words) {
    int i = blockIdx.x * blockDim.x + threadIdx.x;
    int stride = gridDim.x * blockDim.x;
    for (int j = i; j < C_CLS * C_CLS; j += stride) g_counts[j] = 0;
    if (blockIdx.x == 0 && threadIdx.x < 32) {
        int nz = 0;
        #pragma unroll
        for (int k = 0; k < 2; k++)
            nz |= tgt_words[2 * (threadIdx.x * 2 + k) + 1];   // odd words 1..127
        unsigned ball = __ballot_sync(0xffffffffu, nz != 0);
        if (threadIdx.x == 0) {
            g_is64 = (ball == 0u) ? 1 : 0;
            g_done = 0u;
        }
    }
}

// ---------------------------------------------------------------------------
// k1: one warp per row. Fused rowmax + argmax + sumexp + target-logit gather
// + scatter-count. 262 MB streamed once (streaming .cs hint) -> HBM-bound.
// ---------------------------------------------------------------------------
__global__ __launch_bounds__(256) void k_rows(
    const float* __restrict__ outp, const void* __restrict__ tgt)
{
    int warp = (blockIdx.x * 256 + threadIdx.x) >> 5;
    int lane = threadIdx.x & 31;
    if (warp >= B_ROWS) return;

    const float4* rp = (const float4*)(outp + (size_t)warp * C_CLS);

    float vals[32];
    float m  = -INFINITY;
    int   am = 0x7fffffff;

    // Batch 8 independent LDG.128 per lane (MLP), track lane-local max/argmax.
    #pragma unroll
    for (int i = 0; i < 8; i++) {
        int idx4 = lane + i * 32;
        float4 v;
        if (idx4 < C4) v = __ldcs(rp + idx4);
        else           v = make_float4(-INFINITY, -INFINITY, -INFINITY, -INFINITY);
        int base = idx4 * 4;
        vals[4*i+0] = v.x; vals[4*i+1] = v.y; vals[4*i+2] = v.z; vals[4*i+3] = v.w;
        if (v.x > m || (v.x == m && base + 0 < am)) { m = v.x; am = base + 0; }
        if (v.y > m || (v.y == m && base + 1 < am)) { m = v.y; am = base + 1; }
        if (v.z > m || (v.z == m && base + 2 < am)) { m = v.z; am = base + 2; }
        if (v.w > m || (v.w == m && base + 3 < am)) { m = v.w; am = base + 3; }
    }

    // Warp argmax-reduce (first-index tiebreak, matches jnp.argmax).
    #pragma unroll
    for (int off = 16; off; off >>= 1) {
        float om = __shfl_down_sync(0xffffffffu, m,  off);
        int   oa = __shfl_down_sync(0xffffffffu, am, off);
        if (om > m || (om == m && oa < am)) { m = om; am = oa; }
    }
    m  = __shfl_sync(0xffffffffu, m,  0);
    am = __shfl_sync(0xffffffffu, am, 0);

    // Sumexp over register-resident values (padding -INF -> exp = 0).
    float s = 0.0f;
    #pragma unroll
    for (int k = 0; k < 32; k++) s += __expf(vals[k] - m);
    #pragma unroll
    for (int off = 16; off; off >>= 1)
        s += __shfl_down_sync(0xffffffffu, s, off);

    if (lane == 0) {
        long long tl = g_is64 ? ((const long long*)tgt)[warp]
                              : (long long)((const int*)tgt)[warp];
        int t = (int)tl;
        float xt  = outp[(size_t)warp * C_CLS + t];   // L1 hit (row just loaded)
        float glp = xt - m - __logf(s);
        int idx = t * C_CLS + am;
        g_pair[warp] = make_float2(glp, __int_as_float(idx));
        atomicAdd(&g_counts[idx], 1);
    }
}

// ---------------------------------------------------------------------------
// k2: one block per class row. Row-sum of (cost+counts), then write the
// fully-normalized matrix cmn = (cost+counts) * beta / max(1, sum).
// ---------------------------------------------------------------------------
__global__ __launch_bounds__(256) void k_scale(const float* __restrict__ cost) {
    int r = blockIdx.x;
    float v[4];
    float s = 0.0f;
    #pragma unroll
    for (int k = 0; k < 4; k++) {
        int c = threadIdx.x + k * 256;
        float x = 0.0f;
        if (c < C_CLS) {
            int idx = r * C_CLS + c;
            x = cost[idx] + (float)g_counts[idx];
        }
        v[k] = x;
        s += x;
    }
    __shared__ float sh[256];
    sh[threadIdx.x] = s;
    __syncthreads();
    #pragma unroll
    for (int off = 128; off; off >>= 1) {
        if (threadIdx.x < off) sh[threadIdx.x] += sh[threadIdx.x + off];
        __syncthreads();
    }
    float scale = BETA_F / fmaxf(1.0f, sh[0]);
    #pragma unroll
    for (int k = 0; k < 4; k++) {
        int c = threadIdx.x + k * 256;
        if (c < C_CLS) g_cmn[r * C_CLS + c] = v[k] * scale;
    }
}

// ---------------------------------------------------------------------------
// k3: per-sample gather + product. 1 coalesced float2 load + 1 L2 gather.
// Warp-shuffle reduce -> per-block partial; fenced last-block finishes the
// deterministic tree sum and writes -mean.
// ---------------------------------------------------------------------------
__global__ __launch_bounds__(256) void k_dot(float* __restrict__ out) {
    int b = blockIdx.x * 256 + threadIdx.x;
    float2 pr = g_pair[b];                       // exactly B_ROWS threads
    float acc = pr.x * g_cmn[__float_as_int(pr.y)];

    #pragma unroll
    for (int off = 16; off; off >>= 1)
        acc += __shfl_down_sync(0xffffffffu, acc, off);

    __shared__ float shw[8];
    __shared__ bool  is_last;
    int wid = threadIdx.x >> 5;
    if ((threadIdx.x & 31) == 0) shw[wid] = acc;
    __syncthreads();
    if (threadIdx.x == 0) {
        float s = shw[0] + shw[1] + shw[2] + shw[3]
                + shw[4] + shw[5] + shw[6] + shw[7];
        g_partial[blockIdx.x] = s;
        __threadfence();
        unsigned done = atomicAdd(&g_done, 1u);
        is_last = (done == (unsigned)(DOT_BLOCKS - 1));
    }
    __syncthreads();

    if (is_last) {
        __shared__ float sh[DOT_BLOCKS];
        sh[threadIdx.x] = g_partial[threadIdx.x];
        __syncthreads();
        #pragma unroll
        for (int off = DOT_BLOCKS / 2; off; off >>= 1) {
            if (threadIdx.x < off) sh[threadIdx.x] += sh[threadIdx.x + off];
            __syncthreads();
        }
        if (threadIdx.x == 0) out[0] = -sh[0] / (float)B_ROWS;
    }
}

extern "C" void kernel_launch(void* const* d_in, const int* in_sizes, int n_in,
                              void* d_out, int out_size) {
    const float* outputs = (const float*)d_in[0];
    const void*  targets = d_in[1];
    const float* cost    = (const float*)d_in[2];
    float* out = (float*)d_out;

    k_zero <<<1024, 256>>>((const int*)targets);
    k_rows <<<B_ROWS / 8, 256>>>(outputs, targets);      // 8 warps/block
    k_scale<<<C_CLS, 256>>>(cost);
    k_dot  <<<DOT_BLOCKS, 256>>>(out);
}

// round 8
// speedup vs baseline: 1.2358x; 1.0248x over previous
#include <cuda_runtime.h>
#include <math.h>

#define B_ROWS 65536
#define C_CLS  1000
#define C4     250        // 1000 floats = 250 float4 per row
#define BETA_F 3.0f
#define LOG2E_F 1.4426950408889634f
#define DOT_BLOCKS 256

// ---- scratch (no allocations allowed; zero-initialized at module load) ----
__device__ __align__(16) int    g_counts[C_CLS * C_CLS];
__device__ __align__(16) float  g_cmn[C_CLS * C_CLS];   // (cost+counts)*scale
__device__ __align__(16) float2 g_pair[B_ROWS];         // {glp, bits(t*1000+p)}
__device__ float  g_partial[DOT_BLOCKS];
__device__ unsigned int g_done;                          // reset by k_dot last block

// ---------------------------------------------------------------------------
// k1: one warp per row. Inline dtype detect (warp 0 per block), fused
// rowmax+argmax+sumexp, prefetched target & target-logit. 262 MB streamed
// once with .cs -> HBM-bound.
// ---------------------------------------------------------------------------
__global__ __launch_bounds__(256) void k_rows(
    const float* __restrict__ outp, const void* __restrict__ tgt)
{
    __shared__ int sh_is64;
    int tid  = threadIdx.x;
    int lane = tid & 31;

    // dtype detect: int64 targets in [0,1000) have all-zero odd words.
    if (tid < 32) {
        const int* tw = (const int*)tgt;
        int nz = tw[2 * (tid * 2 + 0) + 1] | tw[2 * (tid * 2 + 1) + 1];
        unsigned ball = __ballot_sync(0xffffffffu, nz != 0);
        if (tid == 0) sh_is64 = (ball == 0u) ? 1 : 0;
    }
    __syncthreads();
    int is64 = sh_is64;

    int warp = (blockIdx.x * 256 + tid) >> 5;
    const float*  row = outp + (size_t)warp * C_CLS;
    const float4* rp  = (const float4*)row;

    // Prefetch target index + target logit on lane 0 (overlaps row loads).
    int   t  = 0;
    float xt = 0.0f;
    if (lane == 0) {
        long long tl = is64 ? ((const long long*)tgt)[warp]
                            : (long long)((const int*)tgt)[warp];
        t  = (int)tl;
        xt = __ldg(row + t);
    }

    float vals[32];
    float m  = -INFINITY;
    int   am = 0x7fffffff;

    // 8 independent LDG.128 per lane; strict > keeps first index per lane
    // (iteration order is index-ascending within a lane).
    #pragma unroll
    for (int i = 0; i < 8; i++) {
        int idx4 = lane + i * 32;
        float4 v;
        if (idx4 < C4) v = __ldcs(rp + idx4);
        else           v = make_float4(-INFINITY, -INFINITY, -INFINITY, -INFINITY);
        int base = idx4 * 4;
        vals[4*i+0] = v.x; vals[4*i+1] = v.y; vals[4*i+2] = v.z; vals[4*i+3] = v.w;
        if (v.x > m) { m = v.x; am = base + 0; }
        if (v.y > m) { m = v.y; am = base + 1; }
        if (v.z > m) { m = v.z; am = base + 2; }
        if (v.w > m) { m = v.w; am = base + 3; }
    }

    // Warp argmax-reduce (first-index tiebreak, matches jnp.argmax).
    #pragma unroll
    for (int off = 16; off; off >>= 1) {
        float om = __shfl_down_sync(0xffffffffu, m,  off);
        int   oa = __shfl_down_sync(0xffffffffu, am, off);
        if (om > m || (om == m && oa < am)) { m = om; am = oa; }
    }
    m  = __shfl_sync(0xffffffffu, m,  0);
    am = __shfl_sync(0xffffffffu, am, 0);

    // Sumexp: exp2(fma(v, log2e, -m*log2e)) = FFMA + MUFU per element,
    // 4 accumulators for ILP. Padding -INF -> exp = 0.
    float nml = -m * LOG2E_F;
    float s0 = 0.0f, s1 = 0.0f, s2 = 0.0f, s3 = 0.0f;
    #pragma unroll
    for (int k = 0; k < 32; k += 4) {
        s0 += exp2f(fmaf(vals[k+0], LOG2E_F, nml));
        s1 += exp2f(fmaf(vals[k+1], LOG2E_F, nml));
        s2 += exp2f(fmaf(vals[k+2], LOG2E_F, nml));
        s3 += exp2f(fmaf(vals[k+3], LOG2E_F, nml));
    }
    float s = (s0 + s1) + (s2 + s3);
    #pragma unroll
    for (int off = 16; off; off >>= 1)
        s += __shfl_down_sync(0xffffffffu, s, off);

    if (lane == 0) {
        float glp = xt - m - __logf(s);
        int idx = t * C_CLS + am;
        g_pair[warp] = make_float2(glp, __int_as_float(idx));
        atomicAdd(&g_counts[idx], 1);
    }
}

// ---------------------------------------------------------------------------
// k2: one block per class row, one float4/int4 per thread (250 active).
// cmn = (cost+counts) * beta / max(1, rowsum); zeroes counts row for the
// next call (block-local -> race-free).
// ---------------------------------------------------------------------------
__global__ __launch_bounds__(256) void k_scale(const float* __restrict__ cost) {
    int r  = blockIdx.x;
    int c4 = threadIdx.x;
    float4 res = make_float4(0.f, 0.f, 0.f, 0.f);
    float  s   = 0.0f;
    if (c4 < C4) {
        float4 cv = *(const float4*)(cost + (size_t)r * C_CLS + c4 * 4);
        int4   nv = *(const int4*)(g_counts + (size_t)r * C_CLS + c4 * 4);
        res.x = cv.x + (float)nv.x;
        res.y = cv.y + (float)nv.y;
        res.z = cv.z + (float)nv.z;
        res.w = cv.w + (float)nv.w;
        s = (res.x + res.y) + (res.z + res.w);
    }
    __shared__ float sh[256];
    sh[threadIdx.x] = s;
    __syncthreads();
    #pragma unroll
    for (int off = 128; off; off >>= 1) {
        if (threadIdx.x < off) sh[threadIdx.x] += sh[threadIdx.x + off];
        __syncthreads();
    }
    float scale = BETA_F / fmaxf(1.0f, sh[0]);
    if (c4 < C4) {
        float4 w = make_float4(res.x * scale, res.y * scale,
                               res.z * scale, res.w * scale);
        *(float4*)(g_cmn + (size_t)r * C_CLS + c4 * 4) = w;
        *(int4*)(g_counts + (size_t)r * C_CLS + c4 * 4) = make_int4(0, 0, 0, 0);
    }
}

// ---------------------------------------------------------------------------
// k3: per-sample gather + product (1 coalesced float2 + 1 L2 gather),
// warp-shuffle reduce -> partials; fenced last block finishes the
// deterministic tree sum, writes -mean, resets g_done for the next call.
// ---------------------------------------------------------------------------
__global__ __launch_bounds__(256) void k_dot(float* __restrict__ out) {
    int b = blockIdx.x * 256 + threadIdx.x;
    float2 pr = g_pair[b];                       // exactly B_ROWS threads
    float acc = pr.x * g_cmn[__float_as_int(pr.y)];

    #pragma unroll
    for (int off = 16; off; off >>= 1)
        acc += __shfl_down_sync(0xffffffffu, acc, off);

    __shared__ float shw[8];
    __shared__ bool  is_last;
    int wid = threadIdx.x >> 5;
    if ((threadIdx.x & 31) == 0) shw[wid] = acc;
    __syncthreads();
    if (threadIdx.x == 0) {
        float sB = ((shw[0] + shw[1]) + (shw[2] + shw[3]))
                 + ((shw[4] + shw[5]) + (shw[6] + shw[7]));
        g_partial[blockIdx.x] = sB;
        __threadfence();
        unsigned done = atomicAdd(&g_done, 1u);
        is_last = (done == (unsigned)(DOT_BLOCKS - 1));
    }
    __syncthreads();

    if (is_last) {
        __shared__ float sh[DOT_BLOCKS];
        sh[threadIdx.x] = g_partial[threadIdx.x];
        __syncthreads();
        #pragma unroll
        for (int off = DOT_BLOCKS / 2; off; off >>= 1) {
            if (threadIdx.x < off) sh[threadIdx.x] += sh[threadIdx.x + off];
            __syncthreads();
        }
        if (threadIdx.x == 0) {
            out[0] = -sh[0] / (float)B_ROWS;
            g_done = 0u;                          // ready for next replay
        }
    }
}

extern "C" void kernel_launch(void* const* d_in, const int* in_sizes, int n_in,
                              void* d_out, int out_size) {
    const float* outputs = (const float*)d_in[0];
    const void*  targets = d_in[1];
    const float* cost    = (const float*)d_in[2];
    float* out = (float*)d_out;

    k_rows <<<B_ROWS / 8, 256>>>(outputs, targets);   // 8 warps/block
    k_scale<<<C_CLS, 256>>>(cost);
    k_dot  <<<DOT_BLOCKS, 256>>>(out);
}